// round 5
// baseline (speedup 1.0000x reference)
#include <cuda_runtime.h>
#include <cstdint>

#define T_LEN 8192
#define NTHREADS 256

__device__ __forceinline__ uint32_t rotl32(uint32_t x, int r) {
    return (x << r) | (x >> (32 - r));
}

// Threefry-2x32, 20 rounds, key = (0,42); returns x0^x1 (JAX partitionable fold).
__device__ __forceinline__ uint32_t threefry_xor(uint32_t c0, uint32_t c1) {
    const uint32_t ks0 = 0u, ks1 = 42u;
    const uint32_t ks2 = ks0 ^ ks1 ^ 0x1BD11BDAu;
    uint32_t x0 = c0 + ks0, x1 = c1 + ks1;
#define TF_R4(a,b,c,d) \
    x0 += x1; x1 = rotl32(x1,a); x1 ^= x0; \
    x0 += x1; x1 = rotl32(x1,b); x1 ^= x0; \
    x0 += x1; x1 = rotl32(x1,c); x1 ^= x0; \
    x0 += x1; x1 = rotl32(x1,d); x1 ^= x0;
    TF_R4(13,15,26,6);   x0 += ks1; x1 += ks2 + 1u;
    TF_R4(17,29,16,24);  x0 += ks2; x1 += ks0 + 2u;
    TF_R4(13,15,26,6);   x0 += ks0; x1 += ks1 + 3u;
    TF_R4(17,29,16,24);  x0 += ks1; x1 += ks2 + 4u;
    TF_R4(13,15,26,6);   x0 += ks2; x1 += ks0 + 5u;
#undef TF_R4
    return x0 ^ x1;
}

// One bit-sliced histogram pass: 32 tokens (one per lane) -> 4 per-lane bin counters.
// Lane l owns bins l, l+32, l+64, l+96.
__device__ __forceinline__ void hist_pass(int tok,
                                          uint32_t X0, uint32_t X1, uint32_t X2,
                                          uint32_t X3, uint32_t X4,
                                          uint32_t& c0, uint32_t& c1,
                                          uint32_t& c2, uint32_t& c3) {
    uint32_t bin = (uint32_t)tok & 127u;
    uint32_t B0 = __ballot_sync(0xffffffffu, bin & 1u);
    uint32_t B1 = __ballot_sync(0xffffffffu, bin & 2u);
    uint32_t B2 = __ballot_sync(0xffffffffu, bin & 4u);
    uint32_t B3 = __ballot_sync(0xffffffffu, bin & 8u);
    uint32_t B4 = __ballot_sync(0xffffffffu, bin & 16u);
    uint32_t B5 = __ballot_sync(0xffffffffu, bin & 32u);
    uint32_t B6 = __ballot_sync(0xffffffffu, bin & 64u);
    uint32_t m = (B0 ^ X0) & (B1 ^ X1) & (B2 ^ X2) & (B3 ^ X3) & (B4 ^ X4);
    c0 += __popc(m & ~B5 & ~B6);
    c1 += __popc(m &  B5 & ~B6);
    c2 += __popc(m & ~B5 &  B6);
    c3 += __popc(m &  B5 &  B6);
}

__global__ __launch_bounds__(NTHREADS)
void midi_stats_mlp_kernel(const int* __restrict__ tokens,
                           const float* __restrict__ W1,
                           const float* __restrict__ b1,
                           const float* __restrict__ W2,
                           const float* __restrict__ b2,
                           float* __restrict__ out) {
    __shared__ int hist[128];
    __shared__ unsigned s_sum, s_ssq;
    __shared__ float stats[152];
    __shared__ float h[256];

    const int b = blockIdx.x;
    const int tid = threadIdx.x;
    const uint32_t lane = tid & 31u;

    if (tid < 128) hist[tid] = 0;
    if (tid == 0) { s_sum = 0u; s_ssq = 0u; }
    __syncthreads();

    // Lane-constant bit-select masks for the low 5 bin bits (== lane id).
    const uint32_t X0 = (lane & 1u)  ? 0u : ~0u;
    const uint32_t X1 = (lane & 2u)  ? 0u : ~0u;
    const uint32_t X2 = (lane & 4u)  ? 0u : ~0u;
    const uint32_t X3 = (lane & 8u)  ? 0u : ~0u;
    const uint32_t X4 = (lane & 16u) ? 0u : ~0u;

    // ---- Pass 1: ballot histogram + integer moments (no shared traffic) ----
    const int4* tp = reinterpret_cast<const int4*>(tokens + (size_t)b * T_LEN);
    uint32_t c0 = 0, c1 = 0, c2 = 0, c3 = 0;
    unsigned lsum = 0, lssq = 0;
#pragma unroll
    for (int i = 0; i < 8; i++) {
        int4 v = tp[i * NTHREADS + tid];
        lsum += (unsigned)(v.x + v.y) + (unsigned)(v.z + v.w);
        lssq += (unsigned)(v.x * v.x) + (unsigned)(v.y * v.y)
              + (unsigned)(v.z * v.z) + (unsigned)(v.w * v.w);
        hist_pass(v.x, X0, X1, X2, X3, X4, c0, c1, c2, c3);
        hist_pass(v.y, X0, X1, X2, X3, X4, c0, c1, c2, c3);
        hist_pass(v.z, X0, X1, X2, X3, X4, c0, c1, c2, c3);
        hist_pass(v.w, X0, X1, X2, X3, X4, c0, c1, c2, c3);
    }
    // Per-warp counters -> shared histogram (only 4 atomics per lane, 8 warps).
    atomicAdd(&hist[lane],       (int)c0);
    atomicAdd(&hist[lane + 32],  (int)c1);
    atomicAdd(&hist[lane + 64],  (int)c2);
    atomicAdd(&hist[lane + 96],  (int)c3);

    lsum = __reduce_add_sync(0xffffffffu, lsum);
    lssq = __reduce_add_sync(0xffffffffu, lssq);
    if (lane == 0) {
        atomicAdd(&s_sum, lsum);
        atomicAdd(&s_ssq, lssq);
    }
    __syncthreads();

    // ---- Stage 2: assemble 150-dim stats vector ----
    if (tid < 128) {
        stats[tid] = (float)hist[tid] * (1.0f / 8192.0f);  // f32(8192+1e-8)==8192
    } else if (tid == 128) {
        stats[128] = (float)((double)s_sum / 8192.0);       // mean
    } else if (tid == 129) {
        double m   = (double)s_sum / 8192.0;
        double var = ((double)s_ssq - (double)s_sum * m) / 8191.0;  // unbiased
        stats[129] = (float)sqrt(var);
    } else if (tid < 138) {
        stats[tid] = 0.0f;
    } else if (tid < 150) {
        // harmony: jax.random.uniform(key(42), (1024,12)), partitionable path
        uint32_t idx = (uint32_t)(b * 12 + (tid - 138));
        uint32_t bits = threefry_xor(0u, idx);
        stats[tid] = __uint_as_float((bits >> 9) | 0x3F800000u) - 1.0f;
    }
    __syncthreads();

    // ---- Layer 1: h = relu(stats @ W1 + b1) ----
    float acc = b1[tid];
#pragma unroll 10
    for (int s = 0; s < 150; s++)
        acc = fmaf(stats[s], W1[s * 256 + tid], acc);
    h[tid] = fmaxf(acc, 0.0f);
    __syncthreads();

    // ---- Layer 2: out = h @ W2 + b2 ----
    if (tid < 128) {
        float o = b2[tid];
#pragma unroll 8
        for (int k = 0; k < 256; k++)
            o = fmaf(h[k], W2[k * 128 + tid], o);
        out[(size_t)b * 128 + tid] = o;
    }
}

extern "C" void kernel_launch(void* const* d_in, const int* in_sizes, int n_in,
                              void* d_out, int out_size) {
    const int*   tokens = (const int*)d_in[0];
    const float* W1     = (const float*)d_in[1];
    const float* b1     = (const float*)d_in[2];
    const float* W2     = (const float*)d_in[3];
    const float* b2     = (const float*)d_in[4];
    float* out = (float*)d_out;
    midi_stats_mlp_kernel<<<1024, NTHREADS>>>(tokens, W1, b1, W2, b2, out);
}

// round 6
// speedup vs baseline: 1.0090x; 1.0090x over previous
#include <cuda_runtime.h>
#include <cstdint>

#define T_LEN 8192
#define NTHREADS 128
#define NWARPS 4
#define VOCAB 390
#define HPAD 392   // padded stride for warp histogram copies

__device__ __forceinline__ uint32_t rotl32(uint32_t x, int r) {
    return (x << r) | (x >> (32 - r));
}

// Threefry-2x32, 20 rounds, key = (0,42); returns x0^x1 (JAX partitionable fold).
__device__ __forceinline__ uint32_t threefry_xor(uint32_t c0, uint32_t c1) {
    const uint32_t ks0 = 0u, ks1 = 42u;
    const uint32_t ks2 = ks0 ^ ks1 ^ 0x1BD11BDAu;
    uint32_t x0 = c0 + ks0, x1 = c1 + ks1;
#define TF_R4(a,b,c,d) \
    x0 += x1; x1 = rotl32(x1,a); x1 ^= x0; \
    x0 += x1; x1 = rotl32(x1,b); x1 ^= x0; \
    x0 += x1; x1 = rotl32(x1,c); x1 ^= x0; \
    x0 += x1; x1 = rotl32(x1,d); x1 ^= x0;
    TF_R4(13,15,26,6);   x0 += ks1; x1 += ks2 + 1u;
    TF_R4(17,29,16,24);  x0 += ks2; x1 += ks0 + 2u;
    TF_R4(13,15,26,6);   x0 += ks0; x1 += ks1 + 3u;
    TF_R4(17,29,16,24);  x0 += ks1; x1 += ks2 + 4u;
    TF_R4(13,15,26,6);   x0 += ks2; x1 += ks0 + 5u;
#undef TF_R4
    return x0 ^ x1;
}

__global__ __launch_bounds__(NTHREADS)
void midi_stats_mlp_kernel(const int* __restrict__ tokens,
                           const float* __restrict__ W1,
                           const float* __restrict__ b1,
                           const float* __restrict__ W2,
                           const float* __restrict__ b2,
                           float* __restrict__ out) {
    __shared__ unsigned whist[NWARPS * HPAD];  // per-warp full-vocab histograms
    __shared__ unsigned s_sum, s_ssq;
    __shared__ float stats[152];   // 150 used
    __shared__ float h[256];

    const int b   = blockIdx.x;
    const int tid = threadIdx.x;
    const int wid = tid >> 5;
    const uint32_t lane = tid & 31u;

    // Zero histograms + scalars
#pragma unroll
    for (int i = tid; i < NWARPS * HPAD; i += NTHREADS) whist[i] = 0u;
    if (tid == 0) { s_sum = 0u; s_ssq = 0u; }
    __syncthreads();

    // ---- Hot loop: ONLY histogram increments (2 instr/token) ----
    // Full-vocab bins: moments and pitch histogram are derived in the epilogue.
    const int4* tp = reinterpret_cast<const int4*>(tokens + (size_t)b * T_LEN);
    unsigned* hw = &whist[wid * HPAD];
#pragma unroll 4
    for (int i = 0; i < T_LEN / 4 / NTHREADS; i++) {
        int4 v = tp[i * NTHREADS + tid];
        atomicAdd(&hw[v.x], 1u);
        atomicAdd(&hw[v.y], 1u);
        atomicAdd(&hw[v.z], 1u);
        atomicAdd(&hw[v.w], 1u);
    }
    __syncthreads();

    // ---- Epilogue: fold 4 warp copies; derive pitch hist + exact moments ----
    // Thread t owns vocab values { t, t+128, t+256, t+384(<390) } — all ≡ t (mod 128),
    // so its pitch bin is exactly t.
    {
        unsigned pitchTot = 0, lsum = 0, lssq = 0;
#pragma unroll
        for (int q = 0; q < 4; q++) {
            int v = tid + 128 * q;
            if (v < VOCAB) {
                unsigned tot = whist[v] + whist[HPAD + v]
                             + whist[2 * HPAD + v] + whist[3 * HPAD + v];
                pitchTot += tot;
                lsum += (unsigned)v * tot;
                lssq += (unsigned)(v * v) * tot;
            }
        }
        stats[tid] = (float)pitchTot * (1.0f / 8192.0f);  // f32(8192+1e-8)==8192
        lsum = __reduce_add_sync(0xffffffffu, lsum);
        lssq = __reduce_add_sync(0xffffffffu, lssq);
        if (lane == 0) {
            atomicAdd(&s_sum, lsum);   // max 3.2e6, fits u32
            atomicAdd(&s_ssq, lssq);   // max 1.24e9, fits u32
        }
    }
    __syncthreads();

    // ---- Remaining stats dims ----
    if (tid == 0) {
        double m = (double)s_sum / 8192.0;
        stats[128] = (float)m;                                           // mean
        stats[129] = (float)sqrt(((double)s_ssq - (double)s_sum * m) / 8191.0);  // unbiased std
    }
    if (tid >= 2 && tid < 10) stats[128 + tid] = 0.0f;                   // stats[130..137]
    if (tid >= 10 && tid < 22) {
        // harmony: jax.random.uniform(key(42), (1024,12)), partitionable Threefry
        uint32_t idx = (uint32_t)(b * 12 + (tid - 10));
        uint32_t bits = threefry_xor(0u, idx);
        stats[138 + (tid - 10)] = __uint_as_float((bits >> 9) | 0x3F800000u) - 1.0f;
    }
    __syncthreads();

    // ---- Layer 1: h = relu(stats @ W1 + b1); 2 columns per thread ----
    {
        float a0 = b1[tid], a1 = b1[tid + 128];
#pragma unroll 10
        for (int s = 0; s < 150; s++) {
            float sv = stats[s];
            a0 = fmaf(sv, W1[s * 256 + tid], a0);
            a1 = fmaf(sv, W1[s * 256 + tid + 128], a1);
        }
        h[tid]       = fmaxf(a0, 0.0f);
        h[tid + 128] = fmaxf(a1, 0.0f);
    }
    __syncthreads();

    // ---- Layer 2: out = h @ W2 + b2; 1 column per thread ----
    {
        float o = b2[tid];
#pragma unroll 8
        for (int k = 0; k < 256; k++)
            o = fmaf(h[k], W2[k * 128 + tid], o);
        out[(size_t)b * 128 + tid] = o;
    }
}

extern "C" void kernel_launch(void* const* d_in, const int* in_sizes, int n_in,
                              void* d_out, int out_size) {
    const int*   tokens = (const int*)d_in[0];
    const float* W1     = (const float*)d_in[1];
    const float* b1     = (const float*)d_in[2];
    const float* W2     = (const float*)d_in[3];
    const float* b2     = (const float*)d_in[4];
    float* out = (float*)d_out;
    midi_stats_mlp_kernel<<<1024, NTHREADS>>>(tokens, W1, b1, W2, b2, out);
}

// round 7
// speedup vs baseline: 1.3509x; 1.3388x over previous
#include <cuda_runtime.h>
#include <cstdint>

#define T_LEN 8192
#define NTHREADS 128
#define NWARPS 4

__device__ __forceinline__ uint32_t rotl32(uint32_t x, int r) {
    return (x << r) | (x >> (32 - r));
}

// Threefry-2x32, 20 rounds, key = (0,42); returns x0^x1 (JAX partitionable fold).
__device__ __forceinline__ uint32_t threefry_xor(uint32_t c0, uint32_t c1) {
    const uint32_t ks0 = 0u, ks1 = 42u;
    const uint32_t ks2 = ks0 ^ ks1 ^ 0x1BD11BDAu;
    uint32_t x0 = c0 + ks0, x1 = c1 + ks1;
#define TF_R4(a,b,c,d) \
    x0 += x1; x1 = rotl32(x1,a); x1 ^= x0; \
    x0 += x1; x1 = rotl32(x1,b); x1 ^= x0; \
    x0 += x1; x1 = rotl32(x1,c); x1 ^= x0; \
    x0 += x1; x1 = rotl32(x1,d); x1 ^= x0;
    TF_R4(13,15,26,6);   x0 += ks1; x1 += ks2 + 1u;
    TF_R4(17,29,16,24);  x0 += ks2; x1 += ks0 + 2u;
    TF_R4(13,15,26,6);   x0 += ks0; x1 += ks1 + 3u;
    TF_R4(17,29,16,24);  x0 += ks1; x1 += ks2 + 4u;
    TF_R4(13,15,26,6);   x0 += ks2; x1 += ks0 + 5u;
#undef TF_R4
    return x0 ^ x1;
}

__global__ __launch_bounds__(NTHREADS)
void midi_stats_mlp_kernel(const int* __restrict__ tokens,
                           const float* __restrict__ W1,
                           const float* __restrict__ b1,
                           const float* __restrict__ W2,
                           const float* __restrict__ b2,
                           float* __restrict__ out) {
    // Per-THREAD private byte histograms: counter(t, b) lives at
    // word index (b>>2)*128 + t, byte (b&3). Bank = t%32 = lane -> always
    // conflict-free; each thread touches only its own bytes -> no atomics.
    __shared__ uint32_t priv[32 * NTHREADS];        // 16 KB
    __shared__ uint32_t plo[NWARPS][32], phi[NWARPS][32];
    __shared__ unsigned s_sum, s_ssq;
    __shared__ float stats[152];
    __shared__ float h[256];

    const int b   = blockIdx.x;
    const int tid = threadIdx.x;
    const int wid = tid >> 5;
    const uint32_t lane = tid & 31u;

    // Zero private histogram (32 words per thread, bank=lane, conflict-free)
#pragma unroll
    for (int w = 0; w < 32; w++) priv[w * NTHREADS + tid] = 0u;
    if (tid == 0) { s_sum = 0u; s_ssq = 0u; }
    __syncthreads();

    // ---- Hot loop: byte-RMW histogram + integer moments, NO atomics ----
    const int4* tp = reinterpret_cast<const int4*>(tokens + (size_t)b * T_LEN);
    unsigned char* mybase = reinterpret_cast<unsigned char*>(priv) + tid * 4;
    unsigned lsum = 0, lssq = 0;
#pragma unroll 8
    for (int i = 0; i < T_LEN / 4 / NTHREADS; i++) {
        int4 v = tp[i * NTHREADS + tid];
        lsum += (unsigned)(v.x + v.y) + (unsigned)(v.z + v.w);
        lssq += (unsigned)(v.x * v.x) + (unsigned)(v.y * v.y)
              + (unsigned)(v.z * v.z) + (unsigned)(v.w * v.w);
        // byte offset for bin = ((bin>>2)*128 + t)*4 + (bin&3)
        //                     = t*4 + ((v & 124) << 7) + (v & 3)
        mybase[(((unsigned)v.x & 124u) << 7) + ((unsigned)v.x & 3u)]++;
        mybase[(((unsigned)v.y & 124u) << 7) + ((unsigned)v.y & 3u)]++;
        mybase[(((unsigned)v.z & 124u) << 7) + ((unsigned)v.z & 3u)]++;
        mybase[(((unsigned)v.w & 124u) << 7) + ((unsigned)v.w & 3u)]++;
    }
    // moments: warp reduce + 1 atomic per warp
    lsum = __reduce_add_sync(0xffffffffu, lsum);
    lssq = __reduce_add_sync(0xffffffffu, lssq);
    if (lane == 0) {
        atomicAdd(&s_sum, lsum);
        atomicAdd(&s_ssq, lssq);
    }
    __syncthreads();

    // ---- Fold stage A: per-warp SIMD-in-word sums over 32 lanes ----
    // word w holds bins {4w..4w+3} as bytes; split even/odd bytes into u16
    // fields (sum over 32 lanes <= 32*64 = 2048, no overflow) and REDUX.
#pragma unroll 8
    for (int w = 0; w < 32; w++) {
        uint32_t x  = priv[w * NTHREADS + tid];       // bank=lane, CF
        uint32_t lo = __reduce_add_sync(0xffffffffu, x & 0x00FF00FFu);
        uint32_t hi = __reduce_add_sync(0xffffffffu, (x >> 8) & 0x00FF00FFu);
        if (lane == 0) { plo[wid][w] = lo; phi[wid][w] = hi; }
    }
    __syncthreads();

    // ---- Fold stage B: combine 4 warp partials; bin b handled by thread b ----
    {
        int w = tid >> 2, k = tid & 3;
        int sh = (k >> 1) * 16;
        uint32_t cnt = 0;
#pragma unroll
        for (int q = 0; q < NWARPS; q++) {
            uint32_t p = (k & 1) ? phi[q][w] : plo[q][w];
            cnt += (p >> sh) & 0xFFFFu;
        }
        stats[tid] = (float)cnt * (1.0f / 8192.0f);   // f32(8192+1e-8)==8192
    }

    // ---- Remaining stats dims ----
    if (tid == 0) {
        double m = (double)s_sum / 8192.0;
        stats[128] = (float)m;                                                  // mean
        stats[129] = (float)sqrt(((double)s_ssq - (double)s_sum * m) / 8191.0); // unbiased std
    }
    if (tid >= 2 && tid < 10) stats[128 + tid] = 0.0f;   // stats[130..137]
    if (tid >= 10 && tid < 22) {
        // harmony: jax.random.uniform(key(42), (1024,12)), partitionable Threefry
        uint32_t idx = (uint32_t)(b * 12 + (tid - 10));
        uint32_t bits = threefry_xor(0u, idx);
        stats[138 + (tid - 10)] = __uint_as_float((bits >> 9) | 0x3F800000u) - 1.0f;
    }
    __syncthreads();

    // ---- Layer 1: h = relu(stats @ W1 + b1); 2 columns per thread ----
    {
        float a0 = b1[tid], a1 = b1[tid + 128];
#pragma unroll 10
        for (int s = 0; s < 150; s++) {
            float sv = stats[s];
            a0 = fmaf(sv, W1[s * 256 + tid], a0);
            a1 = fmaf(sv, W1[s * 256 + tid + 128], a1);
        }
        h[tid]       = fmaxf(a0, 0.0f);
        h[tid + 128] = fmaxf(a1, 0.0f);
    }
    __syncthreads();

    // ---- Layer 2: out = h @ W2 + b2; 1 column per thread ----
    {
        float o = b2[tid];
#pragma unroll 8
        for (int k = 0; k < 256; k++)
            o = fmaf(h[k], W2[k * 128 + tid], o);
        out[(size_t)b * 128 + tid] = o;
    }
}

extern "C" void kernel_launch(void* const* d_in, const int* in_sizes, int n_in,
                              void* d_out, int out_size) {
    const int*   tokens = (const int*)d_in[0];
    const float* W1     = (const float*)d_in[1];
    const float* b1     = (const float*)d_in[2];
    const float* W2     = (const float*)d_in[3];
    const float* b2     = (const float*)d_in[4];
    float* out = (float*)d_out;
    midi_stats_mlp_kernel<<<1024, NTHREADS>>>(tokens, W1, b1, W2, b2, out);
}